// round 13
// baseline (speedup 1.0000x reference)
#include <cuda_runtime.h>
#include <cuda_fp16.h>
#include <cstdint>

#define TOKENS 4096
#define DM 1024
#define DF 4096
#define NE 8

// ---------------- device scratch (static, no runtime alloc) ----------------
__device__ int g_cnt[NE];
__device__ int g_tok[NE][TOKENS];
__device__ int g_slot[NE][TOKENS];
__device__ __align__(16) __half g_xh[(size_t)TOKENS * DM];
__device__ __align__(16) __half g_w1h[(size_t)NE * DF * DM];   // [E][N=DF][K=DM]
__device__ __align__(16) __half g_w2h[(size_t)NE * DM * DF];   // [E][N=DM][K=DF]
__device__ __align__(16) __half g_hh[(size_t)NE * TOKENS * DF];
__device__ __align__(16) float  g_buf[(size_t)8 * TOKENS * DM];  // [split*2+slot][token][DM]

// ---------------- helpers ----------------
__device__ __forceinline__ uint32_t smem_u32(const void* p) {
    uint32_t a;
    asm("{ .reg .u64 t; cvta.to.shared.u64 t, %1; cvt.u32.u64 %0, t; }" : "=r"(a) : "l"(p));
    return a;
}
__device__ __forceinline__ void cp16(uint32_t s, const void* g) {
    asm volatile("cp.async.cg.shared.global [%0], [%1], 16;" :: "r"(s), "l"(g) : "memory");
}
__device__ __forceinline__ void cp_commit() {
    asm volatile("cp.async.commit_group;" ::: "memory");
}
__device__ __forceinline__ void cp_wait1() {
    asm volatile("cp.async.wait_group 1;" ::: "memory");
}
#define MMA_F16(acc, a, b)                                                       \
    asm volatile(                                                                \
        "mma.sync.aligned.m16n8k16.row.col.f32.f16.f16.f32 "                     \
        "{%0,%1,%2,%3},{%4,%5,%6,%7},{%8,%9},{%0,%1,%2,%3};"                     \
        : "+f"((acc)[0]), "+f"((acc)[1]), "+f"((acc)[2]), "+f"((acc)[3])         \
        : "r"((a)[0]), "r"((a)[1]), "r"((a)[2]), "r"((a)[3]),                    \
          "r"((b)[0]), "r"((b)[1]))

// ---------------- shared GEMM config ----------------
#define ROWB   80
#define TILEB  (128 * ROWB)          // 10240 B
#define STAGEB (2 * TILEB)           // 20480 B (A tile + B tile)
#define NSTAGE 3
#define SMEMB  (NSTAGE * STAGEB + 512)   // 61952 B; 2 CTAs = 124KB < 228KB
#define GTHREADS 512

// ---------------- transpose+convert tile bodies ----------
__device__ __forceinline__ void conv_tile256(const float* __restrict__ Wp,
                                             __half* __restrict__ oh,
                                             int K, int N, int n0, int k0,
                                             int tid, float (*t)[33]) {
    int tx = tid & 31, ty = tid >> 5;   // 32 x 8
#pragma unroll
    for (int i = 0; i < 4; i++)
        t[ty + 8 * i][tx] = Wp[(size_t)(k0 + ty + 8 * i) * N + n0 + tx];
    __syncthreads();
    int n_l = ty * 4 + (tx >> 3);
    int k_l = (tx & 7) * 2;
#pragma unroll
    for (int rep = 0; rep < 2; rep++) {
        int kk = k_l + rep * 16;
        __half2 h;
        h.x = __float2half_rn(t[kk][n_l]);
        h.y = __float2half_rn(t[kk + 1][n_l]);
        *(__half2*)(oh + (size_t)(n0 + n_l) * K + k0 + kk) = h;
    }
}

__device__ __forceinline__ void conv_tile512(const float* __restrict__ Wp,
                                             __half* __restrict__ oh,
                                             int K, int N, int n0, int k0,
                                             int tid, float (*t)[33]) {
    int tx = tid & 31, ty = tid >> 5;   // 32 x 16
#pragma unroll
    for (int i = 0; i < 2; i++)
        t[ty + 16 * i][tx] = Wp[(size_t)(k0 + ty + 16 * i) * N + n0 + tx];
    __syncthreads();
    int n_l = ty * 2 + (tx >> 4);        // 0..31
    int k_l = (tx & 15) * 2;             // 0..30 even
    __half2 h;
    h.x = __float2half_rn(t[k_l][n_l]);
    h.y = __float2half_rn(t[k_l + 1][n_l]);
    *(__half2*)(oh + (size_t)(n0 + n_l) * K + k0 + k_l) = h;
}

// ---------------- 0) zero counters ----------------
__global__ void zero_cnt_kernel() {
    if (threadIdx.x < NE) g_cnt[threadIdx.x] = 0;
}

// ---------------- 1) fused prep: route | convert_x | convert_w1 (256 thr) --
__global__ void prep_kernel(const float* __restrict__ x,
                            const float* __restrict__ Wg,
                            const float* __restrict__ bg,
                            const float* __restrict__ W1) {
    __shared__ float t[32][33];
    const int bx = blockIdx.x;
    const int tid = threadIdx.x;

    if (bx < 512) {
        // ---- routing ----
        int warp = tid >> 5, lane = tid & 31;
        int token = bx * 8 + warp;
        float acc[NE];
#pragma unroll
        for (int e = 0; e < NE; e++) acc[e] = 0.f;
        const float* xrow = x + (size_t)token * DM;
        for (int k = lane; k < DM; k += 32) {
            float xv = xrow[k];
            const float* wr = Wg + (size_t)k * NE;
#pragma unroll
            for (int e = 0; e < NE; e++) acc[e] += xv * wr[e];
        }
#pragma unroll
        for (int e = 0; e < NE; e++)
#pragma unroll
            for (int o = 16; o > 0; o >>= 1)
                acc[e] += __shfl_xor_sync(0xffffffffu, acc[e], o);
        if (lane == 0) {
            float lg[NE];
#pragma unroll
            for (int e = 0; e < NE; e++) lg[e] = acc[e] + bg[e];
            int e0 = 0;
#pragma unroll
            for (int e = 1; e < NE; e++) if (lg[e] > lg[e0]) e0 = e;
            int e1 = (e0 == 0) ? 1 : 0;
#pragma unroll
            for (int e = 0; e < NE; e++) if (e != e0 && lg[e] > lg[e1]) e1 = e;
            int p0 = atomicAdd(&g_cnt[e0], 1);
            g_tok[e0][p0] = token; g_slot[e0][p0] = 0;
            int p1 = atomicAdd(&g_cnt[e1], 1);
            g_tok[e1][p1] = token; g_slot[e1][p1] = 1;
        }
    } else if (bx < 4608) {
        // ---- convert x ----
        int i = (bx - 512) * 256 + tid;          // float4 index
        float4 v = ((const float4*)x)[i];
        __half2 h0, h1;
        h0.x = __float2half_rn(v.x); h0.y = __float2half_rn(v.y);
        h1.x = __float2half_rn(v.z); h1.y = __float2half_rn(v.w);
        ((__half2*)g_xh)[2 * i]     = h0;
        ((__half2*)g_xh)[2 * i + 1] = h1;
    } else {
        // ---- convert W1 ----
        int j = bx - 4608;                       // [0, 8192)
        int e = j >> 10;
        int rem = j & 1023;
        int n_t = rem & 127;
        int k_t4 = rem >> 7;
        const float* Wp = W1 + (size_t)e * DM * DF;
        __half* oh = g_w1h + (size_t)e * DF * DM;
#pragma unroll
        for (int i = 0; i < 4; i++) {
            __syncthreads();
            conv_tile256(Wp, oh, DM, DF, n_t * 32, (k_t4 * 4 + i) * 32, tid, t);
        }
    }
}

// ---------------- GEMM core: 512 threads, 16 warps (4M x 4N), warp 32x32 ----
template <int KDIM, bool G1>
__device__ __forceinline__ void stage_load(uint32_t sb, int k0,
                                           const __half* __restrict__ A,
                                           const __half* __restrict__ B,
                                           const int* __restrict__ srow, int aBase,
                                           int n0, int tid) {
    int r = tid >> 2, j = tid & 3;           // 128 rows x 4 quads
    uint32_t so = (uint32_t)(r * ROWB + j * 16);
    int arow = G1 ? srow[r] : (aBase + r);
    size_t ga = (size_t)arow * KDIM + k0 + j * 8;
    size_t gb = (size_t)(n0 + r) * KDIM + k0 + j * 8;
    cp16(sb + so,         A + ga);
    cp16(sb + TILEB + so, B + gb);
}

// KSPAN: K covered by this tile (1024 for both GEMM1 and split-4 GEMM2).
// kBase: starting K offset. addBias: add bias (split 0 only for GEMM2).
// plane: g_buf plane base (split*2) for GEMM2.
template <int KSPAN, int KDIM, int NDIM, bool G1>
__device__ __forceinline__ void gemm_body(const float* __restrict__ bias,
                                          char* smem, int e, int m0, int n0,
                                          int kBase, int plane, bool addBias) {
    const int cnt = g_cnt[e];
    if (m0 >= cnt) return;
    constexpr int NT = KSPAN / 32;

    const uint32_t sb = smem_u32(smem);
    const int tid = threadIdx.x, wid = tid >> 5, lane = tid & 31;
    const int warp_m = wid >> 2, warp_n = wid & 3;     // 4 x 4 warps
    const int g = lane >> 2, tg = lane & 3;
    int* srow = (int*)(smem + NSTAGE * STAGEB);
    const int aBase = e * TOKENS + m0;

    if (G1) {
        if (tid < 128) {
            int rr = min(m0 + tid, cnt - 1);
            srow[tid] = g_tok[e][rr];
        }
        __syncthreads();
    }

    const __half* A = G1 ? g_xh : g_hh;
    const __half* B = (G1 ? g_w1h : g_w2h) + (size_t)e * NDIM * KDIM;

    float acc[2][4][4];
#pragma unroll
    for (int i = 0; i < 2; i++)
#pragma unroll
        for (int j = 0; j < 4; j++)
#pragma unroll
            for (int k = 0; k < 4; k++) acc[i][j][k] = 0.f;

    // prologue: stages 0, 1 in flight
    stage_load<KDIM, G1>(sb, kBase, A, B, srow, aBase, n0, tid);
    cp_commit();
    stage_load<KDIM, G1>(sb + STAGEB, kBase + 32, A, B, srow, aBase, n0, tid);
    cp_commit();

    const int aRowBase = warp_m * 32 + g;     // warp tile m=32
    const int bRowBase = warp_n * 32 + g;     // warp tile n=32

    int slot = 0;
    for (int it = 0; it < NT; it++) {
        cp_wait1();
        __syncthreads();
        if (it + 2 < NT) {
            int ns = slot + 2; if (ns >= NSTAGE) ns -= NSTAGE;
            stage_load<KDIM, G1>(sb + ns * STAGEB, kBase + (it + 2) * 32,
                                 A, B, srow, aBase, n0, tid);
        }
        cp_commit();

        const char* st = smem + slot * STAGEB;
#pragma unroll
        for (int ks = 0; ks < 2; ks++) {
            const int colb = (ks * 16 + tg * 2) * 2;
            uint32_t bh[4][2];
#pragma unroll
            for (int nf = 0; nf < 4; nf++) {
                int ro = (bRowBase + nf * 8) * ROWB + colb;
                bh[nf][0] = *(const uint32_t*)(st + TILEB + ro);
                bh[nf][1] = *(const uint32_t*)(st + TILEB + ro + 16);
            }
#pragma unroll
            for (int mf = 0; mf < 2; mf++) {
                int ro = (aRowBase + mf * 16) * ROWB + colb;
                uint32_t a[4];
                a[0] = *(const uint32_t*)(st + ro);
                a[1] = *(const uint32_t*)(st + ro + 8 * ROWB);
                a[2] = *(const uint32_t*)(st + ro + 16);
                a[3] = *(const uint32_t*)(st + ro + 8 * ROWB + 16);
#pragma unroll
                for (int nf = 0; nf < 4; nf++)
                    MMA_F16(acc[mf][nf], a, bh[nf]);
            }
        }
        slot++; if (slot >= NSTAGE) slot = 0;
    }

    // epilogue
#pragma unroll
    for (int mf = 0; mf < 2; mf++) {
        int r0 = m0 + warp_m * 32 + mf * 16 + g;
        int r1 = r0 + 8;
#pragma unroll
        for (int nf = 0; nf < 4; nf++) {
            int col = n0 + warp_n * 32 + nf * 8 + tg * 2;
            float bv0 = addBias ? bias[e * NDIM + col]     : 0.f;
            float bv1 = addBias ? bias[e * NDIM + col + 1] : 0.f;
#pragma unroll
            for (int h = 0; h < 2; h++) {
                int r = h ? r1 : r0;
                if (r >= cnt) continue;
                float v0 = acc[mf][nf][2 * h]     + bv0;
                float v1 = acc[mf][nf][2 * h + 1] + bv1;
                if (G1) {
                    v0 = fmaxf(v0, 0.f);
                    v1 = fmaxf(v1, 0.f);
                    __half2 hh;
                    hh.x = __float2half_rn(v0);
                    hh.y = __float2half_rn(v1);
                    size_t o = ((size_t)(e * TOKENS + r)) * DF + col;
                    *(__half2*)(g_hh + o) = hh;
                } else {
                    int token = g_tok[e][r];
                    int slot2 = g_slot[e][r];
                    float* dst = g_buf + ((size_t)(plane + slot2) * TOKENS + token) * DM + col;
                    *(float2*)dst = make_float2(v0, v1);
                }
            }
        }
    }
}

// ---------------- 2) GEMM1 fused with convert_w2 ---------------------------
__global__ void __launch_bounds__(GTHREADS, 2)
gemm1_fused(const float* __restrict__ b1, const float* __restrict__ W2) {
    extern __shared__ char smem[];
    if (blockIdx.z >= 8) {
        int e = blockIdx.z - 8;
        int b = blockIdx.y * 32 + blockIdx.x;    // [0, 1024)
        int n_t = b & 31;
        int k_t4 = b >> 5;
        const float* Wp = W2 + (size_t)e * DF * DM;
        __half* oh = g_w2h + (size_t)e * DM * DF;
        float (*t)[33] = (float(*)[33])smem;
        int tid = threadIdx.x;
#pragma unroll
        for (int i = 0; i < 4; i++) {
            __syncthreads();
            conv_tile512(Wp, oh, DF, DM, n_t * 32, (k_t4 * 4 + i) * 32, tid, t);
        }
        return;
    }
    gemm_body<DM, DM, DF, true>(b1, smem, blockIdx.z,
                                blockIdx.y * 128, blockIdx.x * 128, 0, 0, true);
}

// ---------------- 3) GEMM2, split-K = 4 ----------------
// z = e*4 + split. Each split covers K range [split*1024, +1024),
// writing plane split*2 + slot. Bias added by split 0 only.
__global__ void __launch_bounds__(GTHREADS, 2)
gemm2_kernel(const float* __restrict__ b2) {
    extern __shared__ char smem[];
    int e = blockIdx.z >> 2;
    int split = blockIdx.z & 3;
    gemm_body<DF / 4, DF, DM, false>(b2, smem, e,
                                     blockIdx.y * 128, blockIdx.x * 128,
                                     split * (DF / 4), split * 2, split == 0);
}

// ---------------- 4) combine: sum 8 planes ----------------
__global__ void combine_kernel(float* __restrict__ out) {
    int i = blockIdx.x * blockDim.x + threadIdx.x;   // float4 index
    const size_t plane4 = (size_t)TOKENS * DM / 4;
    const float4* b = (const float4*)g_buf;
    float4 s = b[i];
#pragma unroll
    for (int p = 1; p < 8; p++) {
        float4 v = b[p * plane4 + i];
        s.x += v.x; s.y += v.y; s.z += v.z; s.w += v.w;
    }
    ((float4*)out)[i] = s;
}

// ---------------- host ----------------
extern "C" void kernel_launch(void* const* d_in, const int* in_sizes, int n_in,
                              void* d_out, int out_size) {
    const float* x  = (const float*)d_in[0];
    const float* Wg = (const float*)d_in[1];
    const float* bg = (const float*)d_in[2];
    const float* W1 = (const float*)d_in[3];
    const float* b1 = (const float*)d_in[4];
    const float* W2 = (const float*)d_in[5];
    const float* b2 = (const float*)d_in[6];
    float* out = (float*)d_out;

    cudaFuncSetAttribute(gemm1_fused,
                         cudaFuncAttributeMaxDynamicSharedMemorySize, SMEMB);
    cudaFuncSetAttribute(gemm2_kernel,
                         cudaFuncAttributeMaxDynamicSharedMemorySize, SMEMB);

    zero_cnt_kernel<<<1, 32>>>();
    prep_kernel<<<12800, 256>>>(x, Wg, bg, W1);
    gemm1_fused<<<dim3(DF / 128, TOKENS / 128, 16), GTHREADS, SMEMB>>>(b1, W2);
    // GEMM2: 8 experts x 4 K-splits in z
    gemm2_kernel<<<dim3(DM / 128, TOKENS / 128, NE * 4), GTHREADS, SMEMB>>>(b2);
    combine_kernel<<<(TOKENS * DM / 4) / 256, 256>>>(out);
}

// round 14
// speedup vs baseline: 1.0284x; 1.0284x over previous
#include <cuda_runtime.h>
#include <cuda_fp16.h>
#include <cstdint>

#define TOKENS 4096
#define DM 1024
#define DF 4096
#define NE 8

// ---------------- device scratch (static, no runtime alloc) ----------------
__device__ int g_cnt[NE];                 // zero at load; re-zeroed by combine
__device__ int g_tok[NE][TOKENS];
__device__ int g_slot[NE][TOKENS];
__device__ __align__(16) __half g_xh[(size_t)TOKENS * DM];
__device__ __align__(16) __half g_w1h[(size_t)NE * DF * DM];   // [E][N=DF][K=DM]
__device__ __align__(16) __half g_w2h[(size_t)NE * DM * DF];   // [E][N=DM][K=DF]
__device__ __align__(16) __half g_hh[(size_t)NE * TOKENS * DF];
__device__ __align__(16) float  g_buf[(size_t)2 * TOKENS * DM];

// ---------------- helpers ----------------
__device__ __forceinline__ uint32_t smem_u32(const void* p) {
    uint32_t a;
    asm("{ .reg .u64 t; cvta.to.shared.u64 t, %1; cvt.u32.u64 %0, t; }" : "=r"(a) : "l"(p));
    return a;
}
__device__ __forceinline__ void cp16(uint32_t s, const void* g) {
    asm volatile("cp.async.cg.shared.global [%0], [%1], 16;" :: "r"(s), "l"(g) : "memory");
}
__device__ __forceinline__ void cp_commit() {
    asm volatile("cp.async.commit_group;" ::: "memory");
}
__device__ __forceinline__ void cp_wait1() {
    asm volatile("cp.async.wait_group 1;" ::: "memory");
}
#define MMA_F16(acc, a, b)                                                       \
    asm volatile(                                                                \
        "mma.sync.aligned.m16n8k16.row.col.f32.f16.f16.f32 "                     \
        "{%0,%1,%2,%3},{%4,%5,%6,%7},{%8,%9},{%0,%1,%2,%3};"                     \
        : "+f"((acc)[0]), "+f"((acc)[1]), "+f"((acc)[2]), "+f"((acc)[3])         \
        : "r"((a)[0]), "r"((a)[1]), "r"((a)[2]), "r"((a)[3]),                    \
          "r"((b)[0]), "r"((b)[1]))

// ---------------- shared GEMM config (R11 best-known) ----------------
#define ROWB   80
#define TILEB  (128 * ROWB)          // 10240 B
#define STAGEB (2 * TILEB)           // 20480 B (A tile + B tile)
#define NSTAGE 3
#define SMEMB  (NSTAGE * STAGEB + 512)   // 61952 B; 2 CTAs = 124KB < 228KB

// ---------------- transpose+convert tile body (256 threads) ----------
__device__ __forceinline__ void conv_tile(const float* __restrict__ Wp,
                                          __half* __restrict__ oh,
                                          int K, int N, int n0, int k0,
                                          int tid, float (*t)[33]) {
    int tx = tid & 31, ty = tid >> 5;   // 32 x 8
#pragma unroll
    for (int i = 0; i < 4; i++)
        t[ty + 8 * i][tx] = Wp[(size_t)(k0 + ty + 8 * i) * N + n0 + tx];
    __syncthreads();
    int n_l = ty * 4 + (tx >> 3);
    int k_l = (tx & 7) * 2;
#pragma unroll
    for (int rep = 0; rep < 2; rep++) {
        int kk = k_l + rep * 16;
        __half2 h;
        h.x = __float2half_rn(t[kk][n_l]);
        h.y = __float2half_rn(t[kk + 1][n_l]);
        *(__half2*)(oh + (size_t)(n0 + n_l) * K + k0 + kk) = h;
    }
}

// ---------------- 1) fused prep: route | convert_x | convert_w1 ------------
__global__ void prep_kernel(const float* __restrict__ x,
                            const float* __restrict__ Wg,
                            const float* __restrict__ bg,
                            const float* __restrict__ W1) {
    __shared__ float t[32][33];
    const int bx = blockIdx.x;
    const int tid = threadIdx.x;

    if (bx < 512) {
        // ---- routing ----
        int warp = tid >> 5, lane = tid & 31;
        int token = bx * 8 + warp;
        float acc[NE];
#pragma unroll
        for (int e = 0; e < NE; e++) acc[e] = 0.f;
        const float* xrow = x + (size_t)token * DM;
        for (int k = lane; k < DM; k += 32) {
            float xv = xrow[k];
            const float* wr = Wg + (size_t)k * NE;
#pragma unroll
            for (int e = 0; e < NE; e++) acc[e] += xv * wr[e];
        }
#pragma unroll
        for (int e = 0; e < NE; e++)
#pragma unroll
            for (int o = 16; o > 0; o >>= 1)
                acc[e] += __shfl_xor_sync(0xffffffffu, acc[e], o);
        if (lane == 0) {
            float lg[NE];
#pragma unroll
            for (int e = 0; e < NE; e++) lg[e] = acc[e] + bg[e];
            int e0 = 0;
#pragma unroll
            for (int e = 1; e < NE; e++) if (lg[e] > lg[e0]) e0 = e;
            int e1 = (e0 == 0) ? 1 : 0;
#pragma unroll
            for (int e = 0; e < NE; e++) if (e != e0 && lg[e] > lg[e1]) e1 = e;
            int p0 = atomicAdd(&g_cnt[e0], 1);
            g_tok[e0][p0] = token; g_slot[e0][p0] = 0;
            int p1 = atomicAdd(&g_cnt[e1], 1);
            g_tok[e1][p1] = token; g_slot[e1][p1] = 1;
        }
    } else if (bx < 4608) {
        // ---- convert x ----
        int i = (bx - 512) * 256 + tid;          // float4 index
        float4 v = ((const float4*)x)[i];
        __half2 h0, h1;
        h0.x = __float2half_rn(v.x); h0.y = __float2half_rn(v.y);
        h1.x = __float2half_rn(v.z); h1.y = __float2half_rn(v.w);
        ((__half2*)g_xh)[2 * i]     = h0;
        ((__half2*)g_xh)[2 * i + 1] = h1;
    } else {
        // ---- convert W1 ----
        int j = bx - 4608;                       // [0, 8192)
        int e = j >> 10;
        int rem = j & 1023;
        int n_t = rem & 127;
        int k_t4 = rem >> 7;
        const float* Wp = W1 + (size_t)e * DM * DF;
        __half* oh = g_w1h + (size_t)e * DF * DM;
#pragma unroll
        for (int i = 0; i < 4; i++) {
            __syncthreads();
            conv_tile(Wp, oh, DM, DF, n_t * 32, (k_t4 * 4 + i) * 32, tid, t);
        }
    }
}

// ---------------- GEMM core: 3-stage cp.async, wait_group 1, 1 sync/iter ----
template <int KDIM, bool G1>
__device__ __forceinline__ void stage_load(uint32_t sb, int k0,
                                           const __half* __restrict__ A,
                                           const __half* __restrict__ B,
                                           const int* __restrict__ srow, int aBase,
                                           int n0, int tid) {
#pragma unroll
    for (int half_ = 0; half_ < 2; half_++) {
        int c = tid + half_ * 256;       // 0..511
        int r = c >> 2, j = c & 3;
        uint32_t so = (uint32_t)(r * ROWB + j * 16);
        int arow = G1 ? srow[r] : (aBase + r);
        size_t ga = (size_t)arow * KDIM + k0 + j * 8;
        size_t gb = (size_t)(n0 + r) * KDIM + k0 + j * 8;
        cp16(sb + so,         A + ga);
        cp16(sb + TILEB + so, B + gb);
    }
}

template <int KDIM, int NDIM, bool G1>
__device__ __forceinline__ void gemm_body(const float* __restrict__ bias,
                                          char* smem, int e, int m0, int n0) {
    const int cnt = g_cnt[e];
    if (m0 >= cnt) return;
    constexpr int NT = KDIM / 32;

    const uint32_t sb = smem_u32(smem);
    const int tid = threadIdx.x, wid = tid >> 5, lane = tid & 31;
    const int warp_m = wid >> 2, warp_n = wid & 3;
    const int g = lane >> 2, tg = lane & 3;
    int* srow = (int*)(smem + NSTAGE * STAGEB);
    const int aBase = e * TOKENS + m0;

    if (G1) {
        if (tid < 128) {
            int rr = min(m0 + tid, cnt - 1);
            srow[tid] = g_tok[e][rr];
        }
        __syncthreads();
    }

    const __half* A = G1 ? g_xh : g_hh;
    const __half* B = (G1 ? g_w1h : g_w2h) + (size_t)e * NDIM * KDIM;

    float acc[4][4][4];
#pragma unroll
    for (int i = 0; i < 4; i++)
#pragma unroll
        for (int j = 0; j < 4; j++)
#pragma unroll
            for (int k = 0; k < 4; k++) acc[i][j][k] = 0.f;

    // prologue: stages 0, 1 in flight
    stage_load<KDIM, G1>(sb, 0, A, B, srow, aBase, n0, tid);
    cp_commit();
    stage_load<KDIM, G1>(sb + STAGEB, 32, A, B, srow, aBase, n0, tid);
    cp_commit();

    const int aRowBase = warp_m * 64 + g;
    const int bRowBase = warp_n * 32 + g;

    int slot = 0;
    for (int it = 0; it < NT; it++) {
        cp_wait1();
        __syncthreads();
        if (it + 2 < NT) {
            int ns = slot + 2; if (ns >= NSTAGE) ns -= NSTAGE;
            stage_load<KDIM, G1>(sb + ns * STAGEB, (it + 2) * 32,
                                 A, B, srow, aBase, n0, tid);
        }
        cp_commit();

        const char* st = smem + slot * STAGEB;
#pragma unroll
        for (int ks = 0; ks < 2; ks++) {
            const int colb = (ks * 16 + tg * 2) * 2;
            uint32_t bh[4][2];
#pragma unroll
            for (int nf = 0; nf < 4; nf++) {
                int ro = (bRowBase + nf * 8) * ROWB + colb;
                bh[nf][0] = *(const uint32_t*)(st + TILEB + ro);
                bh[nf][1] = *(const uint32_t*)(st + TILEB + ro + 16);
            }
#pragma unroll
            for (int mf = 0; mf < 4; mf++) {
                int ro = (aRowBase + mf * 16) * ROWB + colb;
                uint32_t a[4];
                a[0] = *(const uint32_t*)(st + ro);
                a[1] = *(const uint32_t*)(st + ro + 8 * ROWB);
                a[2] = *(const uint32_t*)(st + ro + 16);
                a[3] = *(const uint32_t*)(st + ro + 8 * ROWB + 16);
#pragma unroll
                for (int nf = 0; nf < 4; nf++)
                    MMA_F16(acc[mf][nf], a, bh[nf]);
            }
        }
        slot++; if (slot >= NSTAGE) slot = 0;
    }

    // epilogue
#pragma unroll
    for (int mf = 0; mf < 4; mf++) {
        int r0 = m0 + warp_m * 64 + mf * 16 + g;
        int r1 = r0 + 8;
#pragma unroll
        for (int nf = 0; nf < 4; nf++) {
            int col = n0 + warp_n * 32 + nf * 8 + tg * 2;
            float bv0 = bias[e * NDIM + col];
            float bv1 = bias[e * NDIM + col + 1];
#pragma unroll
            for (int h = 0; h < 2; h++) {
                int r = h ? r1 : r0;
                if (r >= cnt) continue;
                float v0 = acc[mf][nf][2 * h]     + bv0;
                float v1 = acc[mf][nf][2 * h + 1] + bv1;
                if (G1) {
                    v0 = fmaxf(v0, 0.f);
                    v1 = fmaxf(v1, 0.f);
                    __half2 hh;
                    hh.x = __float2half_rn(v0);
                    hh.y = __float2half_rn(v1);
                    size_t o = ((size_t)(e * TOKENS + r)) * DF + col;
                    *(__half2*)(g_hh + o) = hh;
                } else {
                    int token = g_tok[e][r];
                    int slot2 = g_slot[e][r];
                    float* dst = g_buf + ((size_t)slot2 * TOKENS + token) * DM + col;
                    *(float2*)dst = make_float2(v0, v1);
                }
            }
        }
    }
}

// ---------------- 2) GEMM1 fused with convert_w2 ---------------------------
__global__ void __launch_bounds__(256, 2)
gemm1_fused(const float* __restrict__ b1, const float* __restrict__ W2) {
    extern __shared__ char smem[];
    if (blockIdx.z >= 8) {
        int e = blockIdx.z - 8;
        int b = blockIdx.y * 32 + blockIdx.x;    // [0, 1024)
        int n_t = b & 31;
        int k_t4 = b >> 5;
        const float* Wp = W2 + (size_t)e * DF * DM;
        __half* oh = g_w2h + (size_t)e * DM * DF;
        float (*t)[33] = (float(*)[33])smem;
        int tid = threadIdx.x;
#pragma unroll
        for (int i = 0; i < 4; i++) {
            __syncthreads();
            conv_tile(Wp, oh, DF, DM, n_t * 32, (k_t4 * 4 + i) * 32, tid, t);
        }
        return;
    }
    gemm_body<DM, DF, true>(b1, smem, blockIdx.z, blockIdx.y * 128, blockIdx.x * 128);
}

// ---------------- 3) GEMM2 ----------------
__global__ void __launch_bounds__(256, 2)
gemm2_kernel(const float* __restrict__ b2) {
    extern __shared__ char smem[];
    gemm_body<DF, DM, false>(b2, smem, blockIdx.z, blockIdx.y * 128, blockIdx.x * 128);
}

// ---------------- 4) combine (+ reset g_cnt for the next pass) -------------
__global__ void combine_kernel(float* __restrict__ out) {
    int i = blockIdx.x * blockDim.x + threadIdx.x;
    const float4* b0 = (const float4*)g_buf;
    const float4* b1 = (const float4*)(g_buf + (size_t)TOKENS * DM);
    float4 u = b0[i], v = b1[i];
    ((float4*)out)[i] = make_float4(u.x + v.x, u.y + v.y, u.z + v.z, u.w + v.w);
    if (blockIdx.x == 0 && threadIdx.x < NE) g_cnt[threadIdx.x] = 0;
}

// ---------------- host ----------------
extern "C" void kernel_launch(void* const* d_in, const int* in_sizes, int n_in,
                              void* d_out, int out_size) {
    const float* x  = (const float*)d_in[0];
    const float* Wg = (const float*)d_in[1];
    const float* bg = (const float*)d_in[2];
    const float* W1 = (const float*)d_in[3];
    const float* b1 = (const float*)d_in[4];
    const float* W2 = (const float*)d_in[5];
    const float* b2 = (const float*)d_in[6];
    float* out = (float*)d_out;

    cudaFuncSetAttribute(gemm1_fused,
                         cudaFuncAttributeMaxDynamicSharedMemorySize, SMEMB);
    cudaFuncSetAttribute(gemm2_kernel,
                         cudaFuncAttributeMaxDynamicSharedMemorySize, SMEMB);

    // g_cnt is zero at module load and re-zeroed by combine_kernel each pass.
    prep_kernel<<<12800, 256>>>(x, Wg, bg, W1);
    gemm1_fused<<<dim3(DF / 128, TOKENS / 128, 16), 256, SMEMB>>>(b1, W2);
    gemm2_kernel<<<dim3(DM / 128, TOKENS / 128, NE), 256, SMEMB>>>(b2);
    combine_kernel<<<(TOKENS * DM / 4) / 256, 256>>>(out);
}

// round 15
// speedup vs baseline: 1.0507x; 1.0217x over previous
#include <cuda_runtime.h>
#include <cuda_fp16.h>
#include <cstdint>

#define TOKENS 4096
#define DM 1024
#define DF 4096
#define NE 8

// ---------------- device scratch (static, no runtime alloc) ----------------
__device__ int g_cnt[NE];                 // zero at load; re-zeroed by combine
__device__ int g_tok[NE][TOKENS];
__device__ int g_slot[NE][TOKENS];
__device__ __align__(16) __half g_xh[(size_t)TOKENS * DM];
__device__ __align__(16) __half g_w1h[(size_t)NE * DF * DM];   // [E][N=DF][K=DM]
__device__ __align__(16) __half g_w2h[(size_t)NE * DM * DF];   // [E][N=DM][K=DF]
__device__ __align__(16) __half g_hh[(size_t)NE * TOKENS * DF];
__device__ __align__(16) float  g_buf[(size_t)2 * TOKENS * DM];

// ---------------- helpers ----------------
__device__ __forceinline__ uint32_t smem_u32(const void* p) {
    uint32_t a;
    asm("{ .reg .u64 t; cvta.to.shared.u64 t, %1; cvt.u32.u64 %0, t; }" : "=r"(a) : "l"(p));
    return a;
}
__device__ __forceinline__ void cp16(uint32_t s, const void* g) {
    asm volatile("cp.async.cg.shared.global [%0], [%1], 16;" :: "r"(s), "l"(g) : "memory");
}
__device__ __forceinline__ void cp_commit() {
    asm volatile("cp.async.commit_group;" ::: "memory");
}
__device__ __forceinline__ void cp_wait0() {
    asm volatile("cp.async.wait_group 0;" ::: "memory");
}
#define MMA_F16(acc, a, b)                                                       \
    asm volatile(                                                                \
        "mma.sync.aligned.m16n8k16.row.col.f32.f16.f16.f32 "                     \
        "{%0,%1,%2,%3},{%4,%5,%6,%7},{%8,%9},{%0,%1,%2,%3};"                     \
        : "+f"((acc)[0]), "+f"((acc)[1]), "+f"((acc)[2]), "+f"((acc)[3])         \
        : "r"((a)[0]), "r"((a)[1]), "r"((a)[2]), "r"((a)[3]),                    \
          "r"((b)[0]), "r"((b)[1]))

// ---------------- shared GEMM config ----------------
#define ROWB   80
#define TILEB  (128 * ROWB)          // 10240 B
#define STAGEB (2 * TILEB)           // 20480 B (A tile + B tile, BK=32)
#define GROUPB (2 * STAGEB)          // 40960 B (two BK=32 chunks)
#define SMEMB  (2 * GROUPB + 512)    // 82432 B; 2 CTAs = 165KB < 228KB

// ---------------- transpose+convert tile body (256 threads) ----------
__device__ __forceinline__ void conv_tile(const float* __restrict__ Wp,
                                          __half* __restrict__ oh,
                                          int K, int N, int n0, int k0,
                                          int tid, float (*t)[33]) {
    int tx = tid & 31, ty = tid >> 5;   // 32 x 8
#pragma unroll
    for (int i = 0; i < 4; i++)
        t[ty + 8 * i][tx] = Wp[(size_t)(k0 + ty + 8 * i) * N + n0 + tx];
    __syncthreads();
    int n_l = ty * 4 + (tx >> 3);
    int k_l = (tx & 7) * 2;
#pragma unroll
    for (int rep = 0; rep < 2; rep++) {
        int kk = k_l + rep * 16;
        __half2 h;
        h.x = __float2half_rn(t[kk][n_l]);
        h.y = __float2half_rn(t[kk + 1][n_l]);
        *(__half2*)(oh + (size_t)(n0 + n_l) * K + k0 + kk) = h;
    }
}

// ---------------- 1) fused prep: route | convert_x | convert_w1 ------------
__global__ void prep_kernel(const float* __restrict__ x,
                            const float* __restrict__ Wg,
                            const float* __restrict__ bg,
                            const float* __restrict__ W1) {
    __shared__ float t[32][33];
    const int bx = blockIdx.x;
    const int tid = threadIdx.x;

    if (bx < 512) {
        // ---- routing ----
        int warp = tid >> 5, lane = tid & 31;
        int token = bx * 8 + warp;
        float acc[NE];
#pragma unroll
        for (int e = 0; e < NE; e++) acc[e] = 0.f;
        const float* xrow = x + (size_t)token * DM;
        for (int k = lane; k < DM; k += 32) {
            float xv = xrow[k];
            const float* wr = Wg + (size_t)k * NE;
#pragma unroll
            for (int e = 0; e < NE; e++) acc[e] += xv * wr[e];
        }
#pragma unroll
        for (int e = 0; e < NE; e++)
#pragma unroll
            for (int o = 16; o > 0; o >>= 1)
                acc[e] += __shfl_xor_sync(0xffffffffu, acc[e], o);
        if (lane == 0) {
            float lg[NE];
#pragma unroll
            for (int e = 0; e < NE; e++) lg[e] = acc[e] + bg[e];
            int e0 = 0;
#pragma unroll
            for (int e = 1; e < NE; e++) if (lg[e] > lg[e0]) e0 = e;
            int e1 = (e0 == 0) ? 1 : 0;
#pragma unroll
            for (int e = 0; e < NE; e++) if (e != e0 && lg[e] > lg[e1]) e1 = e;
            int p0 = atomicAdd(&g_cnt[e0], 1);
            g_tok[e0][p0] = token; g_slot[e0][p0] = 0;
            int p1 = atomicAdd(&g_cnt[e1], 1);
            g_tok[e1][p1] = token; g_slot[e1][p1] = 1;
        }
    } else if (bx < 4608) {
        // ---- convert x ----
        int i = (bx - 512) * 256 + tid;          // float4 index
        float4 v = ((const float4*)x)[i];
        __half2 h0, h1;
        h0.x = __float2half_rn(v.x); h0.y = __float2half_rn(v.y);
        h1.x = __float2half_rn(v.z); h1.y = __float2half_rn(v.w);
        ((__half2*)g_xh)[2 * i]     = h0;
        ((__half2*)g_xh)[2 * i + 1] = h1;
    } else {
        // ---- convert W1 ----
        int j = bx - 4608;                       // [0, 8192)
        int e = j >> 10;
        int rem = j & 1023;
        int n_t = rem & 127;
        int k_t4 = rem >> 7;
        const float* Wp = W1 + (size_t)e * DM * DF;
        __half* oh = g_w1h + (size_t)e * DF * DM;
#pragma unroll
        for (int i = 0; i < 4; i++) {
            __syncthreads();
            conv_tile(Wp, oh, DM, DF, n_t * 32, (k_t4 * 4 + i) * 32, tid, t);
        }
    }
}

// ---------------- GEMM core: paired-chunk pipeline -------------------------
// 4 smem slots = 2 groups x (2 chunks of BK=32). Per group: wait0 + 1 sync,
// then issue both loads for group g+1, then compute 2 chunks back-to-back.
template <int KDIM, bool G1>
__device__ __forceinline__ void stage_load(uint32_t sb, int k0,
                                           const __half* __restrict__ A,
                                           const __half* __restrict__ B,
                                           const int* __restrict__ srow, int aBase,
                                           int n0, int tid) {
#pragma unroll
    for (int half_ = 0; half_ < 2; half_++) {
        int c = tid + half_ * 256;       // 0..511
        int r = c >> 2, j = c & 3;
        uint32_t so = (uint32_t)(r * ROWB + j * 16);
        int arow = G1 ? srow[r] : (aBase + r);
        size_t ga = (size_t)arow * KDIM + k0 + j * 8;
        size_t gb = (size_t)(n0 + r) * KDIM + k0 + j * 8;
        cp16(sb + so,         A + ga);
        cp16(sb + TILEB + so, B + gb);
    }
}

template <int KDIM, int NDIM, bool G1>
__device__ __forceinline__ void gemm_body(const float* __restrict__ bias,
                                          char* smem, int e, int m0, int n0) {
    const int cnt = g_cnt[e];
    if (m0 >= cnt) return;
    constexpr int NG = KDIM / 64;            // groups of 2 BK=32 chunks

    const uint32_t sb = smem_u32(smem);
    const int tid = threadIdx.x, wid = tid >> 5, lane = tid & 31;
    const int warp_m = wid >> 2, warp_n = wid & 3;
    const int g = lane >> 2, tg = lane & 3;
    int* srow = (int*)(smem + 2 * GROUPB);
    const int aBase = e * TOKENS + m0;

    if (G1) {
        if (tid < 128) {
            int rr = min(m0 + tid, cnt - 1);
            srow[tid] = g_tok[e][rr];
        }
        __syncthreads();
    }

    const __half* A = G1 ? g_xh : g_hh;
    const __half* B = (G1 ? g_w1h : g_w2h) + (size_t)e * NDIM * KDIM;

    float acc[4][4][4];
#pragma unroll
    for (int i = 0; i < 4; i++)
#pragma unroll
        for (int j = 0; j < 4; j++)
#pragma unroll
            for (int k = 0; k < 4; k++) acc[i][j][k] = 0.f;

    // prologue: group 0 (chunks 0, 1) in flight as one commit group
    stage_load<KDIM, G1>(sb,          0,  A, B, srow, aBase, n0, tid);
    stage_load<KDIM, G1>(sb + STAGEB, 32, A, B, srow, aBase, n0, tid);
    cp_commit();

    const int aRowBase = warp_m * 64 + g;
    const int bRowBase = warp_n * 32 + g;

    for (int gi = 0; gi < NG; gi++) {
        cp_wait0();                  // group gi resident
        __syncthreads();             // all warps done with group gi-1 (slots reused below)
        if (gi + 1 < NG) {
            uint32_t sbn = sb + (uint32_t)((gi + 1) & 1) * GROUPB;
            int kb = (gi + 1) * 64;
            stage_load<KDIM, G1>(sbn,          kb,      A, B, srow, aBase, n0, tid);
            stage_load<KDIM, G1>(sbn + STAGEB, kb + 32, A, B, srow, aBase, n0, tid);
            cp_commit();
        }
        const char* gbase = smem + (gi & 1) * GROUPB;
#pragma unroll
        for (int half_ = 0; half_ < 2; half_++) {
            const char* st = gbase + half_ * STAGEB;
#pragma unroll
            for (int ks = 0; ks < 2; ks++) {
                const int colb = (ks * 16 + tg * 2) * 2;
                uint32_t bh[4][2];
#pragma unroll
                for (int nf = 0; nf < 4; nf++) {
                    int ro = (bRowBase + nf * 8) * ROWB + colb;
                    bh[nf][0] = *(const uint32_t*)(st + TILEB + ro);
                    bh[nf][1] = *(const uint32_t*)(st + TILEB + ro + 16);
                }
#pragma unroll
                for (int mf = 0; mf < 4; mf++) {
                    int ro = (aRowBase + mf * 16) * ROWB + colb;
                    uint32_t a[4];
                    a[0] = *(const uint32_t*)(st + ro);
                    a[1] = *(const uint32_t*)(st + ro + 8 * ROWB);
                    a[2] = *(const uint32_t*)(st + ro + 16);
                    a[3] = *(const uint32_t*)(st + ro + 8 * ROWB + 16);
#pragma unroll
                    for (int nf = 0; nf < 4; nf++)
                        MMA_F16(acc[mf][nf], a, bh[nf]);
                }
            }
        }
    }

    // epilogue
#pragma unroll
    for (int mf = 0; mf < 4; mf++) {
        int r0 = m0 + warp_m * 64 + mf * 16 + g;
        int r1 = r0 + 8;
#pragma unroll
        for (int nf = 0; nf < 4; nf++) {
            int col = n0 + warp_n * 32 + nf * 8 + tg * 2;
            float bv0 = bias[e * NDIM + col];
            float bv1 = bias[e * NDIM + col + 1];
#pragma unroll
            for (int h = 0; h < 2; h++) {
                int r = h ? r1 : r0;
                if (r >= cnt) continue;
                float v0 = acc[mf][nf][2 * h]     + bv0;
                float v1 = acc[mf][nf][2 * h + 1] + bv1;
                if (G1) {
                    v0 = fmaxf(v0, 0.f);
                    v1 = fmaxf(v1, 0.f);
                    __half2 hh;
                    hh.x = __float2half_rn(v0);
                    hh.y = __float2half_rn(v1);
                    size_t o = ((size_t)(e * TOKENS + r)) * DF + col;
                    *(__half2*)(g_hh + o) = hh;
                } else {
                    int token = g_tok[e][r];
                    int slot2 = g_slot[e][r];
                    float* dst = g_buf + ((size_t)slot2 * TOKENS + token) * DM + col;
                    *(float2*)dst = make_float2(v0, v1);
                }
            }
        }
    }
}

// ---------------- 2) GEMM1 fused with convert_w2 ---------------------------
__global__ void __launch_bounds__(256, 2)
gemm1_fused(const float* __restrict__ b1, const float* __restrict__ W2) {
    extern __shared__ char smem[];
    if (blockIdx.z >= 8) {
        int e = blockIdx.z - 8;
        int b = blockIdx.y * 32 + blockIdx.x;    // [0, 1024)
        int n_t = b & 31;
        int k_t4 = b >> 5;
        const float* Wp = W2 + (size_t)e * DF * DM;
        __half* oh = g_w2h + (size_t)e * DM * DF;
        float (*t)[33] = (float(*)[33])smem;
        int tid = threadIdx.x;
#pragma unroll
        for (int i = 0; i < 4; i++) {
            __syncthreads();
            conv_tile(Wp, oh, DF, DM, n_t * 32, (k_t4 * 4 + i) * 32, tid, t);
        }
        return;
    }
    gemm_body<DM, DF, true>(b1, smem, blockIdx.z, blockIdx.y * 128, blockIdx.x * 128);
}

// ---------------- 3) GEMM2 ----------------
__global__ void __launch_bounds__(256, 2)
gemm2_kernel(const float* __restrict__ b2) {
    extern __shared__ char smem[];
    gemm_body<DF, DM, false>(b2, smem, blockIdx.z, blockIdx.y * 128, blockIdx.x * 128);
}

// ---------------- 4) combine (+ reset g_cnt for the next pass) -------------
__global__ void combine_kernel(float* __restrict__ out) {
    int i = blockIdx.x * blockDim.x + threadIdx.x;
    const float4* b0 = (const float4*)g_buf;
    const float4* b1 = (const float4*)(g_buf + (size_t)TOKENS * DM);
    float4 u = b0[i], v = b1[i];
    ((float4*)out)[i] = make_float4(u.x + v.x, u.y + v.y, u.z + v.z, u.w + v.w);
    if (blockIdx.x == 0 && threadIdx.x < NE) g_cnt[threadIdx.x] = 0;
}

// ---------------- host ----------------
extern "C" void kernel_launch(void* const* d_in, const int* in_sizes, int n_in,
                              void* d_out, int out_size) {
    const float* x  = (const float*)d_in[0];
    const float* Wg = (const float*)d_in[1];
    const float* bg = (const float*)d_in[2];
    const float* W1 = (const float*)d_in[3];
    const float* b1 = (const float*)d_in[4];
    const float* W2 = (const float*)d_in[5];
    const float* b2 = (const float*)d_in[6];
    float* out = (float*)d_out;

    cudaFuncSetAttribute(gemm1_fused,
                         cudaFuncAttributeMaxDynamicSharedMemorySize, SMEMB);
    cudaFuncSetAttribute(gemm2_kernel,
                         cudaFuncAttributeMaxDynamicSharedMemorySize, SMEMB);

    // g_cnt is zero at module load and re-zeroed by combine_kernel each pass.
    prep_kernel<<<12800, 256>>>(x, Wg, bg, W1);
    gemm1_fused<<<dim3(DF / 128, TOKENS / 128, 16), 256, SMEMB>>>(b1, W2);
    gemm2_kernel<<<dim3(DM / 128, TOKENS / 128, NE), 256, SMEMB>>>(b2);
    combine_kernel<<<(TOKENS * DM / 4) / 256, 256>>>(out);
}

// round 16
// speedup vs baseline: 1.0593x; 1.0082x over previous
#include <cuda_runtime.h>
#include <cuda_fp16.h>
#include <cstdint>

#define TOKENS 4096
#define DM 1024
#define DF 4096
#define NE 8

// ---------------- device scratch (static, no runtime alloc) ----------------
__device__ int g_cnt[NE];                 // zero at load; re-zeroed by reset_kernel
__device__ int g_tok[NE][TOKENS];
__device__ int g_slot[NE][TOKENS];
__device__ __align__(16) __half g_xh[(size_t)TOKENS * DM];
__device__ __align__(16) __half g_w1h[(size_t)NE * DF * DM];   // [E][N=DF][K=DM]
__device__ __align__(16) __half g_w2h[(size_t)NE * DM * DF];   // [E][N=DM][K=DF]
__device__ __align__(16) __half g_hh[(size_t)NE * TOKENS * DF];

// ---------------- helpers ----------------
__device__ __forceinline__ uint32_t smem_u32(const void* p) {
    uint32_t a;
    asm("{ .reg .u64 t; cvta.to.shared.u64 t, %1; cvt.u32.u64 %0, t; }" : "=r"(a) : "l"(p));
    return a;
}
__device__ __forceinline__ void cp16(uint32_t s, const void* g) {
    asm volatile("cp.async.cg.shared.global [%0], [%1], 16;" :: "r"(s), "l"(g) : "memory");
}
__device__ __forceinline__ void cp_commit() {
    asm volatile("cp.async.commit_group;" ::: "memory");
}
__device__ __forceinline__ void cp_wait0() {
    asm volatile("cp.async.wait_group 0;" ::: "memory");
}
#define MMA_F16(acc, a, b)                                                       \
    asm volatile(                                                                \
        "mma.sync.aligned.m16n8k16.row.col.f32.f16.f16.f32 "                     \
        "{%0,%1,%2,%3},{%4,%5,%6,%7},{%8,%9},{%0,%1,%2,%3};"                     \
        : "+f"((acc)[0]), "+f"((acc)[1]), "+f"((acc)[2]), "+f"((acc)[3])         \
        : "r"((a)[0]), "r"((a)[1]), "r"((a)[2]), "r"((a)[3]),                    \
          "r"((b)[0]), "r"((b)[1]))

// ---------------- shared GEMM config ----------------
#define ROWB   80
#define TILEB  (128 * ROWB)          // 10240 B
#define STAGEB (2 * TILEB)           // 20480 B (A tile + B tile, BK=32)
#define GROUPB (2 * STAGEB)          // 40960 B (two BK=32 chunks)
#define SMEMB  (2 * GROUPB + 512)    // 82432 B; 2 CTAs = 165KB < 228KB

// ---------------- transpose+convert tile body (256 threads) ----------
__device__ __forceinline__ void conv_tile(const float* __restrict__ Wp,
                                          __half* __restrict__ oh,
                                          int K, int N, int n0, int k0,
                                          int tid, float (*t)[33]) {
    int tx = tid & 31, ty = tid >> 5;   // 32 x 8
#pragma unroll
    for (int i = 0; i < 4; i++)
        t[ty + 8 * i][tx] = Wp[(size_t)(k0 + ty + 8 * i) * N + n0 + tx];
    __syncthreads();
    int n_l = ty * 4 + (tx >> 3);
    int k_l = (tx & 7) * 2;
#pragma unroll
    for (int rep = 0; rep < 2; rep++) {
        int kk = k_l + rep * 16;
        __half2 h;
        h.x = __float2half_rn(t[kk][n_l]);
        h.y = __float2half_rn(t[kk + 1][n_l]);
        *(__half2*)(oh + (size_t)(n0 + n_l) * K + k0 + kk) = h;
    }
}

// ---------------- 1) fused prep: route | convert_x | convert_w1 | zero out -
__global__ void prep_kernel(const float* __restrict__ x,
                            const float* __restrict__ Wg,
                            const float* __restrict__ bg,
                            const float* __restrict__ W1,
                            float* __restrict__ out) {
    __shared__ float t[32][33];
    const int bx = blockIdx.x;
    const int tid = threadIdx.x;

    if (bx < 512) {
        // ---- routing ----
        int warp = tid >> 5, lane = tid & 31;
        int token = bx * 8 + warp;
        float acc[NE];
#pragma unroll
        for (int e = 0; e < NE; e++) acc[e] = 0.f;
        const float* xrow = x + (size_t)token * DM;
        for (int k = lane; k < DM; k += 32) {
            float xv = xrow[k];
            const float* wr = Wg + (size_t)k * NE;
#pragma unroll
            for (int e = 0; e < NE; e++) acc[e] += xv * wr[e];
        }
#pragma unroll
        for (int e = 0; e < NE; e++)
#pragma unroll
            for (int o = 16; o > 0; o >>= 1)
                acc[e] += __shfl_xor_sync(0xffffffffu, acc[e], o);
        if (lane == 0) {
            float lg[NE];
#pragma unroll
            for (int e = 0; e < NE; e++) lg[e] = acc[e] + bg[e];
            int e0 = 0;
#pragma unroll
            for (int e = 1; e < NE; e++) if (lg[e] > lg[e0]) e0 = e;
            int e1 = (e0 == 0) ? 1 : 0;
#pragma unroll
            for (int e = 0; e < NE; e++) if (e != e0 && lg[e] > lg[e1]) e1 = e;
            int p0 = atomicAdd(&g_cnt[e0], 1);
            g_tok[e0][p0] = token; g_slot[e0][p0] = 0;
            int p1 = atomicAdd(&g_cnt[e1], 1);
            g_tok[e1][p1] = token; g_slot[e1][p1] = 1;
        }
    } else if (bx < 4608) {
        // ---- convert x ----
        int i = (bx - 512) * 256 + tid;          // float4 index
        float4 v = ((const float4*)x)[i];
        __half2 h0, h1;
        h0.x = __float2half_rn(v.x); h0.y = __float2half_rn(v.y);
        h1.x = __float2half_rn(v.z); h1.y = __float2half_rn(v.w);
        ((__half2*)g_xh)[2 * i]     = h0;
        ((__half2*)g_xh)[2 * i + 1] = h1;
    } else if (bx < 12800) {
        // ---- convert W1 ----
        int j = bx - 4608;                       // [0, 8192)
        int e = j >> 10;
        int rem = j & 1023;
        int n_t = rem & 127;
        int k_t4 = rem >> 7;
        const float* Wp = W1 + (size_t)e * DM * DF;
        __half* oh = g_w1h + (size_t)e * DF * DM;
#pragma unroll
        for (int i = 0; i < 4; i++) {
            __syncthreads();
            conv_tile(Wp, oh, DM, DF, n_t * 32, (k_t4 * 4 + i) * 32, tid, t);
        }
    } else {
        // ---- zero output (GEMM2 accumulates into it with atomics) ----
        int i = (bx - 12800) * 256 + tid;        // float4 index
        ((float4*)out)[i] = make_float4(0.f, 0.f, 0.f, 0.f);
    }
}

// ---------------- GEMM core: paired-chunk pipeline (R15-proven) ------------
template <int KDIM, bool G1>
__device__ __forceinline__ void stage_load(uint32_t sb, int k0,
                                           const __half* __restrict__ A,
                                           const __half* __restrict__ B,
                                           const int* __restrict__ srow, int aBase,
                                           int n0, int tid) {
#pragma unroll
    for (int half_ = 0; half_ < 2; half_++) {
        int c = tid + half_ * 256;       // 0..511
        int r = c >> 2, j = c & 3;
        uint32_t so = (uint32_t)(r * ROWB + j * 16);
        int arow = G1 ? srow[r] : (aBase + r);
        size_t ga = (size_t)arow * KDIM + k0 + j * 8;
        size_t gb = (size_t)(n0 + r) * KDIM + k0 + j * 8;
        cp16(sb + so,         A + ga);
        cp16(sb + TILEB + so, B + gb);
    }
}

template <int KDIM, int NDIM, bool G1>
__device__ __forceinline__ void gemm_body(const float* __restrict__ bias,
                                          char* smem, int e, int m0, int n0,
                                          float* __restrict__ out) {
    const int cnt = g_cnt[e];
    if (m0 >= cnt) return;
    constexpr int NG = KDIM / 64;            // groups of 2 BK=32 chunks

    const uint32_t sb = smem_u32(smem);
    const int tid = threadIdx.x, wid = tid >> 5, lane = tid & 31;
    const int warp_m = wid >> 2, warp_n = wid & 3;
    const int g = lane >> 2, tg = lane & 3;
    int* srow = (int*)(smem + 2 * GROUPB);
    const int aBase = e * TOKENS + m0;

    if (G1) {
        if (tid < 128) {
            int rr = min(m0 + tid, cnt - 1);
            srow[tid] = g_tok[e][rr];
        }
        __syncthreads();
    }

    const __half* A = G1 ? g_xh : g_hh;
    const __half* B = (G1 ? g_w1h : g_w2h) + (size_t)e * NDIM * KDIM;

    float acc[4][4][4];
#pragma unroll
    for (int i = 0; i < 4; i++)
#pragma unroll
        for (int j = 0; j < 4; j++)
#pragma unroll
            for (int k = 0; k < 4; k++) acc[i][j][k] = 0.f;

    // prologue: group 0 (chunks 0, 1) in flight as one commit group
    stage_load<KDIM, G1>(sb,          0,  A, B, srow, aBase, n0, tid);
    stage_load<KDIM, G1>(sb + STAGEB, 32, A, B, srow, aBase, n0, tid);
    cp_commit();

    const int aRowBase = warp_m * 64 + g;
    const int bRowBase = warp_n * 32 + g;

    for (int gi = 0; gi < NG; gi++) {
        cp_wait0();                  // group gi resident
        __syncthreads();             // all warps done with group gi-1 (slots reused below)
        if (gi + 1 < NG) {
            uint32_t sbn = sb + (uint32_t)((gi + 1) & 1) * GROUPB;
            int kb = (gi + 1) * 64;
            stage_load<KDIM, G1>(sbn,          kb,      A, B, srow, aBase, n0, tid);
            stage_load<KDIM, G1>(sbn + STAGEB, kb + 32, A, B, srow, aBase, n0, tid);
            cp_commit();
        }
        const char* gbase = smem + (gi & 1) * GROUPB;
#pragma unroll
        for (int half_ = 0; half_ < 2; half_++) {
            const char* st = gbase + half_ * STAGEB;
#pragma unroll
            for (int ks = 0; ks < 2; ks++) {
                const int colb = (ks * 16 + tg * 2) * 2;
                uint32_t bh[4][2];
#pragma unroll
                for (int nf = 0; nf < 4; nf++) {
                    int ro = (bRowBase + nf * 8) * ROWB + colb;
                    bh[nf][0] = *(const uint32_t*)(st + TILEB + ro);
                    bh[nf][1] = *(const uint32_t*)(st + TILEB + ro + 16);
                }
#pragma unroll
                for (int mf = 0; mf < 4; mf++) {
                    int ro = (aRowBase + mf * 16) * ROWB + colb;
                    uint32_t a[4];
                    a[0] = *(const uint32_t*)(st + ro);
                    a[1] = *(const uint32_t*)(st + ro + 8 * ROWB);
                    a[2] = *(const uint32_t*)(st + ro + 16);
                    a[3] = *(const uint32_t*)(st + ro + 8 * ROWB + 16);
#pragma unroll
                    for (int nf = 0; nf < 4; nf++)
                        MMA_F16(acc[mf][nf], a, bh[nf]);
                }
            }
        }
    }

    // epilogue
#pragma unroll
    for (int mf = 0; mf < 4; mf++) {
        int r0 = m0 + warp_m * 64 + mf * 16 + g;
        int r1 = r0 + 8;
#pragma unroll
        for (int nf = 0; nf < 4; nf++) {
            int col = n0 + warp_n * 32 + nf * 8 + tg * 2;
            float bv0 = bias[e * NDIM + col];
            float bv1 = bias[e * NDIM + col + 1];
#pragma unroll
            for (int h = 0; h < 2; h++) {
                int r = h ? r1 : r0;
                if (r >= cnt) continue;
                float v0 = acc[mf][nf][2 * h]     + bv0;
                float v1 = acc[mf][nf][2 * h + 1] + bv1;
                if (G1) {
                    v0 = fmaxf(v0, 0.f);
                    v1 = fmaxf(v1, 0.f);
                    __half2 hh;
                    hh.x = __float2half_rn(v0);
                    hh.y = __float2half_rn(v1);
                    size_t o = ((size_t)(e * TOKENS + r)) * DF + col;
                    *(__half2*)(g_hh + o) = hh;
                } else {
                    // out zeroed by prep; each element gets exactly 2 expert
                    // contributions -> atomicAdd order-invariant (bit-exact).
                    int token = g_tok[e][r];
                    float* dst = out + (size_t)token * DM + col;
                    atomicAdd(dst,     v0);
                    atomicAdd(dst + 1, v1);
                }
            }
        }
    }
}

// ---------------- 2) GEMM1 fused with convert_w2 ---------------------------
__global__ void __launch_bounds__(256, 2)
gemm1_fused(const float* __restrict__ b1, const float* __restrict__ W2) {
    extern __shared__ char smem[];
    if (blockIdx.z >= 8) {
        int e = blockIdx.z - 8;
        int b = blockIdx.y * 32 + blockIdx.x;    // [0, 1024)
        int n_t = b & 31;
        int k_t4 = b >> 5;
        const float* Wp = W2 + (size_t)e * DF * DM;
        __half* oh = g_w2h + (size_t)e * DM * DF;
        float (*t)[33] = (float(*)[33])smem;
        int tid = threadIdx.x;
#pragma unroll
        for (int i = 0; i < 4; i++) {
            __syncthreads();
            conv_tile(Wp, oh, DF, DM, n_t * 32, (k_t4 * 4 + i) * 32, tid, t);
        }
        return;
    }
    gemm_body<DM, DF, true>(b1, smem, blockIdx.z,
                            blockIdx.y * 128, blockIdx.x * 128, nullptr);
}

// ---------------- 3) GEMM2 (accumulates directly into out) ----------------
__global__ void __launch_bounds__(256, 2)
gemm2_kernel(const float* __restrict__ b2, float* __restrict__ out) {
    extern __shared__ char smem[];
    gemm_body<DF, DM, false>(b2, smem, blockIdx.z,
                             blockIdx.y * 128, blockIdx.x * 128, out);
}

// ---------------- 4) reset routing counters for the next pass --------------
__global__ void reset_kernel() {
    if (threadIdx.x < NE) g_cnt[threadIdx.x] = 0;
}

// ---------------- host ----------------
extern "C" void kernel_launch(void* const* d_in, const int* in_sizes, int n_in,
                              void* d_out, int out_size) {
    const float* x  = (const float*)d_in[0];
    const float* Wg = (const float*)d_in[1];
    const float* bg = (const float*)d_in[2];
    const float* W1 = (const float*)d_in[3];
    const float* b1 = (const float*)d_in[4];
    const float* W2 = (const float*)d_in[5];
    const float* b2 = (const float*)d_in[6];
    float* out = (float*)d_out;

    cudaFuncSetAttribute(gemm1_fused,
                         cudaFuncAttributeMaxDynamicSharedMemorySize, SMEMB);
    cudaFuncSetAttribute(gemm2_kernel,
                         cudaFuncAttributeMaxDynamicSharedMemorySize, SMEMB);

    // prep: route | convert_x | convert_w1 | zero-out  (g_cnt zero at load /
    // re-zeroed by reset_kernel each pass)
    prep_kernel<<<12800 + TOKENS * DM / 4 / 256, 256>>>(x, Wg, bg, W1, out);
    gemm1_fused<<<dim3(DF / 128, TOKENS / 128, 16), 256, SMEMB>>>(b1, W2);
    gemm2_kernel<<<dim3(DM / 128, TOKENS / 128, NE), 256, SMEMB>>>(b2, out);
    reset_kernel<<<1, 32>>>();
}